// round 16
// baseline (speedup 1.0000x reference)
#include <cuda_runtime.h>
#include <mma.h>

using namespace nvcuda;

#define B_ROWS   131072
#define RES_DIM  100
#define KPAD     104
#define TMG      64              // rows per group-tile
#define NT64     (B_ROWS / TMG)  // 2048 tiles
#define NCH      6
#define H1       128
#define H2       64
#define H3       32
#define CF_ITERS 5
#define CF_K     0.02f
#define NTHREADS 1024
#define GSIZE    512

// padded leading dims (all ≡ 4 mod 32 floats -> conflict-free fragment loads)
#define A_LD   108
#define W1_LD  132
#define W2_LD  68
#define W3_LD  36

// smem layout (floats) — weights shared, activations per group
#define OFF_W1  0                          // 104*132 = 13728
#define OFF_W2  (OFF_W1 + KPAD*W1_LD)      // 128*68  = 8704
#define OFF_W3  (OFF_W2 + H1*W2_LD)        // 64*36   = 2304
#define OFF_W4  (OFF_W3 + H2*W3_LD)        // 32
#define OFF_B1  (OFF_W4 + 32)              // 128
#define OFF_B2  (OFF_B1 + H1)              // 64
#define OFF_B3  (OFF_B2 + H2)              // 32
#define OFF_B4  (OFF_B3 + H3)              // 8 (pad)
#define OFF_ACT (OFF_B4 + 8)               // 25000
#define GA_FLOATS (TMG*A_LD)               // 6912  (res / h2)
#define GB_FLOATS (TMG*W1_LD)              // 8448  (h1 / h3)
#define GRP_FLOATS (GA_FLOATS + GB_FLOATS) // 15360
#define SMEM_FLOATS (OFF_ACT + 2*GRP_FLOATS)
#define SMEM_BYTES  (SMEM_FLOATS * 4)      // 222,880 B

__device__ __forceinline__ float fsigmoid(float x) {
    return 1.0f / (1.0f + __expf(-x));
}

__device__ __forceinline__ void gbar(int g) {
    asm volatile("bar.sync %0, %1;" :: "r"(g + 1), "r"(GSIZE) : "memory");
}

__global__ __launch_bounds__(NTHREADS, 1)
void chambers_mlp_kernel(
    const float* __restrict__ res,
    const float* __restrict__ W1, const float* __restrict__ b1,
    const float* __restrict__ W2, const float* __restrict__ b2,
    const float* __restrict__ W3, const float* __restrict__ b3,
    const float* __restrict__ W4, const float* __restrict__ b4,
    float* __restrict__ raw_out)
{
    extern __shared__ float sm[];
    float* sW1 = sm + OFF_W1;
    float* sW2 = sm + OFF_W2;
    float* sW3 = sm + OFF_W3;
    float* sW4 = sm + OFF_W4;
    float* sb1 = sm + OFF_B1;
    float* sb2 = sm + OFF_B2;
    float* sb3 = sm + OFF_B3;
    float* sb4 = sm + OFF_B4;

    const int c      = blockIdx.y;
    const int tid    = threadIdx.x;
    const int g      = tid >> 9;            // group 0 / 1
    const int tg     = tid & (GSIZE - 1);   // tid within group
    const int w      = (tid >> 5) & 15;     // warp within group

    float* sA = sm + OFF_ACT + g * GRP_FLOATS;              // res (ld 108) / h2 (ld 68)
    float* sB = sm + OFF_ACT + g * GRP_FLOATS + GA_FLOATS;  // h1 (ld 132) / h3 (ld 36)

    // ---- load chamber weights (all 1024 threads; tf32 pre-rounded) ----
    for (int i = tid; i < KPAD * H1; i += NTHREADS) {
        int k = i >> 7, n = i & (H1 - 1);
        float v = (k < RES_DIM) ? W1[(size_t)c * RES_DIM * H1 + i] : 0.0f;
        sW1[k * W1_LD + n] = wmma::__float_to_tf32(v);
    }
    for (int i = tid; i < H1 * H2; i += NTHREADS) {
        int k = i >> 6, n = i & (H2 - 1);
        sW2[k * W2_LD + n] = wmma::__float_to_tf32(W2[(size_t)c * H1 * H2 + i]);
    }
    for (int i = tid; i < H2 * H3; i += NTHREADS) {
        int k = i >> 5, n = i & (H3 - 1);
        sW3[k * W3_LD + n] = wmma::__float_to_tf32(W3[(size_t)c * H2 * H3 + i]);
    }
    if (tid < H3)  sW4[tid] = W4[c * H3 + tid];
    if (tid < H1)  sb1[tid] = b1[c * H1 + tid];
    if (tid < H2)  sb2[tid] = b2[c * H2 + tid];
    if (tid < H3)  sb3[tid] = b3[c * H3 + tid];
    if (tid == 0)  sb4[0]   = b4[c];
    __syncthreads();

    // ---- per-group independent tile chain over 64-row tiles ----
    for (int t = blockIdx.x * 2 + g; t < NT64; t += gridDim.x * 2) {
        const int m0 = t * TMG;

        // ---- stage res tile [64 x 104] @ ld 108, tf32 pre-rounded ----
        for (int i = tg; i < TMG * KPAD; i += GSIZE) {
            int r = i / KPAD;
            int k = i - r * KPAD;
            float v = (k < RES_DIM) ? res[(size_t)(m0 + r) * RES_DIM + k] : 0.0f;
            sA[r * A_LD + k] = wmma::__float_to_tf32(v);
        }
        gbar(g);

        // ---- L1: [64,104]@[104,128] -> sB (ld 132). 16 warps: 4 row x 4 col(32) ----
        {
            const int wr = w >> 2;    // 0..3 -> 16-row stripes
            const int wc = w & 3;     // 0..3 -> 32-col stripes
            wmma::fragment<wmma::accumulator, 16, 16, 8, float> acc[2];
            #pragma unroll
            for (int j = 0; j < 2; j++) wmma::fill_fragment(acc[j], 0.0f);
            #pragma unroll
            for (int kk = 0; kk < KPAD; kk += 8) {
                wmma::fragment<wmma::matrix_a, 16, 16, 8, wmma::precision::tf32, wmma::row_major> a;
                wmma::fragment<wmma::matrix_b, 16, 16, 8, wmma::precision::tf32, wmma::row_major> b[2];
                wmma::load_matrix_sync(a, sA + (wr * 16) * A_LD + kk, A_LD);
                #pragma unroll
                for (int j = 0; j < 2; j++)
                    wmma::load_matrix_sync(b[j], sW1 + kk * W1_LD + wc * 32 + j * 16, W1_LD);
                #pragma unroll
                for (int j = 0; j < 2; j++)
                    wmma::mma_sync(acc[j], a, b[j], acc[j]);
            }
            #pragma unroll
            for (int j = 0; j < 2; j++)
                wmma::store_matrix_sync(sB + (wr * 16) * W1_LD + wc * 32 + j * 16,
                                        acc[j], W1_LD, wmma::mem_row_major);
        }
        gbar(g);

        // ---- bias1 + silu (tf32 re-round), h1 @ ld 132 ----
        for (int i = tg; i < TMG * H1; i += GSIZE) {
            int r = i >> 7, n = i & (H1 - 1);
            float h = sB[r * W1_LD + n] + sb1[n];
            sB[r * W1_LD + n] = wmma::__float_to_tf32(h * fsigmoid(h));
        }
        gbar(g);

        // ---- L2: [64,128]@[128,64] -> sA (ld 68). 16 warps: 4 row x 4 col(16) ----
        {
            const int wr = w >> 2;
            const int wc = w & 3;
            wmma::fragment<wmma::accumulator, 16, 16, 8, float> acc;
            wmma::fill_fragment(acc, 0.0f);
            #pragma unroll
            for (int kk = 0; kk < H1; kk += 8) {
                wmma::fragment<wmma::matrix_a, 16, 16, 8, wmma::precision::tf32, wmma::row_major> a;
                wmma::fragment<wmma::matrix_b, 16, 16, 8, wmma::precision::tf32, wmma::row_major> b;
                wmma::load_matrix_sync(a, sB + (wr * 16) * W1_LD + kk, W1_LD);
                wmma::load_matrix_sync(b, sW2 + kk * W2_LD + wc * 16, W2_LD);
                wmma::mma_sync(acc, a, b, acc);
            }
            wmma::store_matrix_sync(sA + (wr * 16) * W2_LD + wc * 16,
                                    acc, W2_LD, wmma::mem_row_major);
        }
        gbar(g);

        // ---- bias2 + silu (tf32 re-round), h2 @ ld 68 ----
        for (int i = tg; i < TMG * H2; i += GSIZE) {
            int r = i >> 6, n = i & (H2 - 1);
            float h = sA[r * W2_LD + n] + sb2[n];
            sA[r * W2_LD + n] = wmma::__float_to_tf32(h * fsigmoid(h));
        }
        gbar(g);

        // ---- L3: [64,64]@[64,32] -> sB (ld 36). warps 0..7: 4 row x 2 col ----
        if (w < 8) {
            const int wr = w >> 1;    // 0..3 -> 16-row stripes
            const int wc = w & 1;     // 0..1 -> 16-col stripes
            wmma::fragment<wmma::accumulator, 16, 16, 8, float> acc;
            wmma::fill_fragment(acc, 0.0f);
            #pragma unroll
            for (int kk = 0; kk < H2; kk += 8) {
                wmma::fragment<wmma::matrix_a, 16, 16, 8, wmma::precision::tf32, wmma::row_major> a;
                wmma::fragment<wmma::matrix_b, 16, 16, 8, wmma::precision::tf32, wmma::row_major> b;
                wmma::load_matrix_sync(a, sA + (wr * 16) * W2_LD + kk, W2_LD);
                wmma::load_matrix_sync(b, sW3 + kk * W3_LD + wc * 16, W3_LD);
                wmma::mma_sync(acc, a, b, acc);
            }
            wmma::store_matrix_sync(sB + (wr * 16) * W3_LD + wc * 16, acc, W3_LD,
                                    wmma::mem_row_major);
        }
        gbar(g);

        // ---- L4: per-row: sum_j silu(D3[j]+b3[j]) * W4[j] + b4 ----
        if (tg < TMG) {
            float accv = sb4[0];
            #pragma unroll
            for (int j = 0; j < H3; j++) {
                int jj = (j + tg) & (H3 - 1);   // rotation: conflict-free at ld 36
                float v = sB[tg * W3_LD + jj] + sb3[jj];
                accv += (v * fsigmoid(v)) * sW4[jj];
            }
            raw_out[(size_t)(m0 + tg) * NCH + c] = accv;
        }
        gbar(g);  // protect sA/sB before next tile
    }
}

__global__ __launch_bounds__(256)
void coupling_kernel(const float* __restrict__ raw,
                     const float* __restrict__ coupling,
                     const float* __restrict__ decay,
                     float* __restrict__ act_out)
{
    __shared__ float sc[NCH * NCH];
    __shared__ float sd[NCH];
    if (threadIdx.x < NCH * NCH) sc[threadIdx.x] = coupling[threadIdx.x] * CF_K;
    if (threadIdx.x < NCH)       sd[threadIdx.x] = decay[threadIdx.x];
    __syncthreads();

    const int b = blockIdx.x * blockDim.x + threadIdx.x;
    if (b >= B_ROWS) return;

    float r[NCH], a[NCH];
    #pragma unroll
    for (int j = 0; j < NCH; j++) {
        r[j] = raw[(size_t)b * NCH + j];
        a[j] = fsigmoid(r[j]);
    }
    #pragma unroll
    for (int it = 0; it < CF_ITERS; it++) {
        float d[NCH];
        #pragma unroll
        for (int j = 0; j < NCH; j++) d[j] = 0.0f;
        #pragma unroll
        for (int i = 0; i < NCH; i++) {
            float wv = a[i] * sd[i];
            #pragma unroll
            for (int j = 0; j < NCH; j++) d[j] += wv * sc[i * NCH + j];
        }
        #pragma unroll
        for (int j = 0; j < NCH; j++) a[j] = fsigmoid(r[j] + d[j]);
    }
    #pragma unroll
    for (int j = 0; j < NCH; j++) act_out[(size_t)b * NCH + j] = a[j];
}

extern "C" void kernel_launch(void* const* d_in, const int* in_sizes, int n_in,
                              void* d_out, int out_size) {
    const float* res      = (const float*)d_in[0];
    const float* W1       = (const float*)d_in[1];
    const float* b1       = (const float*)d_in[2];
    const float* W2       = (const float*)d_in[3];
    const float* b2       = (const float*)d_in[4];
    const float* W3       = (const float*)d_in[5];
    const float* b3       = (const float*)d_in[6];
    const float* W4       = (const float*)d_in[7];
    const float* b4       = (const float*)d_in[8];
    const float* coupling = (const float*)d_in[9];
    const float* decay    = (const float*)d_in[10];

    float* out     = (float*)d_out;
    float* act_out = out;                                // act (B,6)
    float* raw_out = out + (size_t)B_ROWS * NCH;         // raw (B,6)

    cudaFuncSetAttribute(chambers_mlp_kernel,
                         cudaFuncAttributeMaxDynamicSharedMemorySize, SMEM_BYTES);

    dim3 grid(74, NCH);  // 444 CTAs x 2 groups = 888 independent tile chains
    chambers_mlp_kernel<<<grid, NTHREADS, SMEM_BYTES>>>(res, W1, b1, W2, b2, W3, b3, W4, b4, raw_out);

    coupling_kernel<<<B_ROWS / 256, 256>>>(raw_out, coupling, decay, act_out);
}